// round 13
// baseline (speedup 1.0000x reference)
#include <cuda_runtime.h>
#include <cuda_bf16.h>
#include <cstdint>

// Deformable Conv3d via portable HMMA (mma.sync.m16n8k16.bf16, hi/lo split).
// R13: R12 + (a) B fragments as ONE uint4 {bh0,bh1,bl0,bl1} per (ks,j)
//      -> per-ks MMA loop with tiny live register set;
//      (b) two taps per barrier round (4 A buffers, 14 barriers not 27)
//      -> doubled latency-hiding stretches in both phases.
//      MTILE=64 / 256 thr / 256 blocks -> 2 independent blocks per SM.

namespace {
constexpr int B_ = 2, CIN_ = 64, COUT_ = 64, D_ = 8, H_ = 32, W_ = 32, K_ = 27;
constexpr int P_ = D_ * H_ * W_;              // 8192
constexpr int MTILE = 64;
constexpr int THREADS = 256;
constexpr int NBLK = (B_ * P_) / MTILE;       // 256

constexpr int ABUF = 16384;                   // one A buffer: hi 8K | lo 8K
constexpr int SM_TOTAL = 4 * ABUF;            // 65536
constexpr unsigned FULL = 0xffffffffu;
}

__device__ __align__(256) float g_xT[B_ * P_ * CIN_];   // channels-last x
// B fragments, uint4 units: [kt][jg(8)][ks(4)][lane(32)] = {bh0,bh1,bl0,bl1}
__device__ __align__(256) uint32_t g_wF[K_ * 8 * 4 * 32 * 4];

// ---------------- helpers ----------------
__device__ __forceinline__ uint32_t smem_u32(const void* p) {
    uint32_t a;
    asm("{ .reg .u64 t; cvta.to.shared.u64 t, %1; cvt.u32.u64 %0, t; }"
        : "=r"(a) : "l"(p));
    return a;
}
__device__ __forceinline__ uint32_t bf16x2(float hi_elem, float lo_elem) {
    uint32_t r;
    asm("cvt.rn.bf16x2.f32 %0, %1, %2;" : "=r"(r) : "f"(hi_elem), "f"(lo_elem));
    return r;
}
__device__ __forceinline__ void ldm_x4(uint32_t* r, uint32_t addr) {
    asm volatile("ldmatrix.sync.aligned.m8n8.x4.shared.b16 {%0,%1,%2,%3}, [%4];"
                 : "=r"(r[0]), "=r"(r[1]), "=r"(r[2]), "=r"(r[3]) : "r"(addr));
}
__device__ __forceinline__ void mma_bf16(float* c, const uint32_t* a,
                                         uint32_t b0, uint32_t b1) {
    asm volatile(
        "mma.sync.aligned.m16n8k16.row.col.f32.bf16.bf16.f32 "
        "{%0,%1,%2,%3}, {%4,%5,%6,%7}, {%8,%9}, {%0,%1,%2,%3};"
        : "+f"(c[0]), "+f"(c[1]), "+f"(c[2]), "+f"(c[3])
        : "r"(a[0]), "r"(a[1]), "r"(a[2]), "r"(a[3]), "r"(b0), "r"(b1));
}
__device__ __forceinline__ void bar_pair(int id) {
    asm volatile("bar.sync %0, 64;" :: "r"(id) : "memory");
}

// ---------------- prep ----------------
__global__ void prep_kernel(const float* __restrict__ x,
                            const float* __restrict__ w) {
    const int stride = gridDim.x * blockDim.x;
    const int tid = blockIdx.x * blockDim.x + threadIdx.x;

    // x [b][c][p] -> xT [b][p][c]
    for (int i = tid; i < B_ * CIN_ * P_; i += stride) {
        int s = i % P_;
        int c = (i / P_) % CIN_;
        int b = i / (P_ * CIN_);
        g_xT[(b * P_ + s) * CIN_ + c] = x[i];
    }

    // weight [o][c][k] -> B fragments [kt][jg][ks][lane][uu]
    // uu: 0=bh reg0, 1=bh reg1, 2=bl reg0, 3=bl reg1
    for (int i = tid; i < K_ * 8 * 4 * 32 * 4; i += stride) {
        int uu   = i & 3;
        int ln   = (i >> 2) & 31;
        int ks   = (i >> 7) & 3;
        int jg   = (i >> 9) & 7;
        int kt   = i >> 12;
        int reg  = uu & 1;
        int hl   = uu >> 1;
        int n = jg * 8 + (ln >> 2);
        int c = ks * 16 + (ln & 3) * 2 + reg * 8;
        float v0 = w[(n * CIN_ + c) * K_ + kt];
        float v1 = w[(n * CIN_ + c + 1) * K_ + kt];
        __nv_bfloat16 h0 = __float2bfloat16(v0);
        __nv_bfloat16 h1 = __float2bfloat16(v1);
        uint32_t valu;
        if (hl == 0) {
            valu = ((uint32_t)__bfloat16_as_ushort(h1) << 16) |
                   (uint32_t)__bfloat16_as_ushort(h0);
        } else {
            __nv_bfloat16 l0 = __float2bfloat16(v0 - __bfloat162float(h0));
            __nv_bfloat16 l1 = __float2bfloat16(v1 - __bfloat162float(h1));
            valu = ((uint32_t)__bfloat16_as_ushort(l1) << 16) |
                   (uint32_t)__bfloat16_as_ushort(l0);
        }
        g_wF[i] = valu;
    }
}

// ---------------- main ----------------
__global__ __launch_bounds__(THREADS, 2)
void deform_hmma_kernel(const float* __restrict__ offset,
                        const float* __restrict__ bias,
                        float* __restrict__ out) {
    extern __shared__ __align__(1024) char smem[];
    const uint32_t sb = smem_u32(smem);

    const int tid  = threadIdx.x;
    const int lane = tid & 31;
    const int warp = tid >> 5;               // 8 warps
    const int blk  = blockIdx.x;
    const int b    = blk >> 7;
    const int p0   = (blk & 127) * MTILE;

    const float* offB = offset + (size_t)b * 3 * K_ * P_;
    const char*  xb   = reinterpret_cast<const char*>(g_xT + (size_t)b * P_ * CIN_);

    // sampling role: 8 points per warp
    const int half = lane >> 4;
    const int c4   = lane & 15;
    const int pl_base = warp * 8;
    const char* base2 = xb + (uint32_t)(c4 << 4);
    uint32_t wAoff[8];
#pragma unroll
    for (int i = 0; i < 8; i++) {
        int pl = pl_base + i;
        wAoff[i] = (uint32_t)(pl * 128 + ((c4 * 8) ^ ((pl & 7) << 4)));
    }

    // mma role: warp (mt, nt) owns D[mt*16..+15][nt*32..+31]
    const int mt = warp >> 1, nt = warp & 1;
    const int rowA = mt * 16 + (lane & 15);
    const uint32_t aBaseOff = (uint32_t)(rowA * 128);
    const uint32_t aXor = (uint32_t)((rowA & 7) << 4);
    const uint32_t aKh  = (uint32_t)((lane >> 4) << 4);

    float acc[4][4];
#pragma unroll
    for (int j = 0; j < 4; j++)
#pragma unroll
        for (int q = 0; q < 4; q++) acc[j][q] = 0.f;

    const uint4* gF = reinterpret_cast<const uint4*>(g_wF);

    // ---- sample one tap into buffer `bf` (0..3) ----
    auto sample_tap = [&](int kt, int bf) {
        char* AhP = smem + bf * ABUF;
        char* AlP = AhP + 8192;
        const int kd = kt / 9, kh3 = (kt / 3) % 3, kw3 = kt % 3;
        const float* offk = offB + 3 * kt * P_;
#pragma unroll
        for (int i = 0; i < 8; i++) {
            const int p  = p0 + pl_base + i;
            const int od = p >> 10, oh = (p >> 5) & 31, ow = p & 31;

            float zd = (float)(od - 1 + kd)  + __ldg(offk + p);
            float zh = (float)(oh - 1 + kh3) + __ldg(offk + P_ + p);
            float zw = (float)(ow - 1 + kw3) + __ldg(offk + 2 * P_ + p);

            float fd = floorf(zd); int d0 = (int)fd; float rd = zd - fd;
            float fh = floorf(zh); int h0 = (int)fh; float rh = zh - fh;
            float fw = floorf(zw); int w0 = (int)fw; float rw = zw - fw;

            float wd = half ? (((unsigned)(d0 + 1) < (unsigned)D_) ? rd : 0.f)
                            : (((unsigned)d0 < (unsigned)D_) ? 1.f - rd : 0.f);
            float wh0 = ((unsigned)h0       < (unsigned)H_) ? 1.f - rh : 0.f;
            float wh1 = ((unsigned)(h0 + 1) < (unsigned)H_) ? rh       : 0.f;
            float ww0 = ((unsigned)w0       < (unsigned)W_) ? 1.f - rw : 0.f;
            float ww1 = ((unsigned)(w0 + 1) < (unsigned)W_) ? rw       : 0.f;

            // linear AND-wrap index (wrapped corners carry weight 0)
            const int s0 = (d0 + half) * 1024 + h0 * 32 + w0;
            const uint32_t i0 = ((uint32_t)s0        & 8191u) << 8;
            const uint32_t i1 = ((uint32_t)(s0 + 1)  & 8191u) << 8;
            const uint32_t i2 = ((uint32_t)(s0 + 32) & 8191u) << 8;
            const uint32_t i3 = ((uint32_t)(s0 + 33) & 8191u) << 8;

            const float wdh0 = wd * wh0, wdh1 = wd * wh1;
            const float g0 = wdh0 * ww0, g1 = wdh0 * ww1;
            const float g2 = wdh1 * ww0, g3 = wdh1 * ww1;

            float4 v0 = __ldg(reinterpret_cast<const float4*>(base2 + i0));
            float4 v1 = __ldg(reinterpret_cast<const float4*>(base2 + i1));
            float4 v2 = __ldg(reinterpret_cast<const float4*>(base2 + i2));
            float4 v3 = __ldg(reinterpret_cast<const float4*>(base2 + i3));

            float ax = g0 * v0.x + g1 * v1.x + g2 * v2.x + g3 * v3.x;
            float ay = g0 * v0.y + g1 * v1.y + g2 * v2.y + g3 * v3.y;
            float az = g0 * v0.z + g1 * v1.z + g2 * v2.z + g3 * v3.z;
            float aw = g0 * v0.w + g1 * v1.w + g2 * v2.w + g3 * v3.w;

            ax += __shfl_down_sync(FULL, ax, 16);
            ay += __shfl_down_sync(FULL, ay, 16);
            az += __shfl_down_sync(FULL, az, 16);
            aw += __shfl_down_sync(FULL, aw, 16);

            if (half == 0) {
                uint32_t h01 = bf16x2(ay, ax);       // hi=ch+1, lo=ch+0
                uint32_t h23 = bf16x2(aw, az);
                float hx = __uint_as_float(h01 << 16);
                float hy = __uint_as_float(h01 & 0xffff0000u);
                float hz = __uint_as_float(h23 << 16);
                float hww = __uint_as_float(h23 & 0xffff0000u);
                uint32_t l01 = bf16x2(ay - hy, ax - hx);
                uint32_t l23 = bf16x2(aw - hww, az - hz);
                *reinterpret_cast<uint2*>(AhP + wAoff[i]) = make_uint2(h01, h23);
                *reinterpret_cast<uint2*>(AlP + wAoff[i]) = make_uint2(l01, l23);
            }
        }
    };

    // ---- mma one tap from buffer `bf` ----
    auto mma_tap = [&](int kt, int bf) {
        const uint32_t AhB = sb + bf * ABUF;
        const uint32_t AlB = AhB + 8192;
        const size_t ktBase = (size_t)(kt * 8 + nt * 4) * 128 + lane;
#pragma unroll
        for (int ks = 0; ks < 4; ks++) {
            uint32_t ah[4], al[4];
            const uint32_t aoff = aBaseOff + (((uint32_t)(ks * 32) + aKh) ^ aXor);
            ldm_x4(ah, AhB + aoff);
            ldm_x4(al, AlB + aoff);
#pragma unroll
            for (int j = 0; j < 4; j++) {
                uint4 q = __ldg(gF + ktBase + (size_t)(j * 128 + ks * 32));
                mma_bf16(acc[j], ah, q.x, q.y);   // Ah*Bh
                mma_bf16(acc[j], al, q.x, q.y);   // Al*Bh
                mma_bf16(acc[j], ah, q.z, q.w);   // Ah*Bl
            }
        }
    };

    // ---- prologue: sample taps 0,1 into bufs 0,1 (pair 0) ----
    sample_tap(0, 0);
    sample_tap(1, 1);
    bar_pair(mt + 1);

    // ---- 14 rounds; round r: taps {2r, 2r+1} from buf pair (r&1) ----
#pragma unroll 1
    for (int r = 0; r < 14; r++) {
        const int pr = r & 1;
        const int c0 = 2 * r;

        // sample next pair into the other buffer pair
        const int n0 = c0 + 2;
        if (n0 < K_)     sample_tap(n0,     2 * (pr ^ 1));
        if (n0 + 1 < K_) sample_tap(n0 + 1, 2 * (pr ^ 1) + 1);

        // mma current pair
        mma_tap(c0, 2 * pr);
        if (c0 + 1 < K_) mma_tap(c0 + 1, 2 * pr + 1);

        bar_pair(mt + 1);
    }

    // ---- epilogue: D fragment scatter + bias ----
    const int m = lane >> 2;
    const int p = p0 + mt * 16 + m;
#pragma unroll
    for (int j = 0; j < 4; j++) {
        const int n = nt * 32 + j * 8 + 2 * (lane & 3);
        const float bv0 = __ldg(&bias[n]);
        const float bv1 = __ldg(&bias[n + 1]);
        float* o0 = out + ((size_t)(b * COUT_ + n)) * P_ + p;
        o0[0]      = acc[j][0] + bv0;
        o0[P_]     = acc[j][1] + bv1;
        o0[8]      = acc[j][2] + bv0;
        o0[P_ + 8] = acc[j][3] + bv1;
    }
}

extern "C" void kernel_launch(void* const* d_in, const int* in_sizes, int n_in,
                              void* d_out, int out_size) {
    const float* x      = (const float*)d_in[0];
    const float* offset = (const float*)d_in[1];
    const float* weight = (const float*)d_in[2];
    const float* bias   = (const float*)d_in[3];
    float* out = (float*)d_out;

    cudaFuncSetAttribute(deform_hmma_kernel,
                         cudaFuncAttributeMaxDynamicSharedMemorySize, SM_TOTAL);
    prep_kernel<<<256, 256>>>(x, weight);
    deform_hmma_kernel<<<NBLK, THREADS, SM_TOTAL>>>(offset, bias, out);
}

// round 14
// speedup vs baseline: 1.1549x; 1.1549x over previous
#include <cuda_runtime.h>
#include <cuda_fp16.h>
#include <cstdint>

// Deformable Conv3d via portable HMMA — R14: fp16 split-B 2-term.
//   D = Ah * (Bh + Bl): A sampled fp32 -> fp16 (single plane),
//   B pre-split fp16 hi/lo in prep. Error ~1.5e-4 << 1e-3 gate.
//   R12 loop structure (single tap/round, 2 A buffers, per-pair barriers),
//   MTILE=64 / 256 thr / 256 blocks -> 2 independent blocks per SM.

namespace {
constexpr int B_ = 2, CIN_ = 64, COUT_ = 64, D_ = 8, H_ = 32, W_ = 32, K_ = 27;
constexpr int P_ = D_ * H_ * W_;              // 8192
constexpr int MTILE = 64;
constexpr int THREADS = 256;
constexpr int NBLK = (B_ * P_) / MTILE;       // 256

constexpr int ABUF = 8192;                    // one A buffer (fp16, 64x128B)
constexpr int SM_TOTAL = 2 * ABUF;            // 16384
constexpr unsigned FULL = 0xffffffffu;
}

__device__ __align__(256) float g_xT[B_ * P_ * CIN_];   // channels-last x
// B fragments, uint4 units: [kt][jg(8)][ks(4)][lane(32)] = {bh0,bh1,bl0,bl1} fp16
__device__ __align__(256) uint32_t g_wF[K_ * 8 * 4 * 32 * 4];

// ---------------- helpers ----------------
__device__ __forceinline__ uint32_t smem_u32(const void* p) {
    uint32_t a;
    asm("{ .reg .u64 t; cvta.to.shared.u64 t, %1; cvt.u32.u64 %0, t; }"
        : "=r"(a) : "l"(p));
    return a;
}
__device__ __forceinline__ uint32_t f16x2(float hi_elem, float lo_elem) {
    uint32_t r;
    asm("cvt.rn.f16x2.f32 %0, %1, %2;" : "=r"(r) : "f"(hi_elem), "f"(lo_elem));
    return r;
}
__device__ __forceinline__ void ldm_x4(uint32_t* r, uint32_t addr) {
    asm volatile("ldmatrix.sync.aligned.m8n8.x4.shared.b16 {%0,%1,%2,%3}, [%4];"
                 : "=r"(r[0]), "=r"(r[1]), "=r"(r[2]), "=r"(r[3]) : "r"(addr));
}
__device__ __forceinline__ void mma_f16(float* c, const uint32_t* a,
                                        uint32_t b0, uint32_t b1) {
    asm volatile(
        "mma.sync.aligned.m16n8k16.row.col.f32.f16.f16.f32 "
        "{%0,%1,%2,%3}, {%4,%5,%6,%7}, {%8,%9}, {%0,%1,%2,%3};"
        : "+f"(c[0]), "+f"(c[1]), "+f"(c[2]), "+f"(c[3])
        : "r"(a[0]), "r"(a[1]), "r"(a[2]), "r"(a[3]), "r"(b0), "r"(b1));
}
__device__ __forceinline__ void bar_pair(int id) {
    asm volatile("bar.sync %0, 64;" :: "r"(id) : "memory");
}

// ---------------- prep ----------------
__global__ void prep_kernel(const float* __restrict__ x,
                            const float* __restrict__ w) {
    const int stride = gridDim.x * blockDim.x;
    const int tid = blockIdx.x * blockDim.x + threadIdx.x;

    // x [b][c][p] -> xT [b][p][c]
    for (int i = tid; i < B_ * CIN_ * P_; i += stride) {
        int s = i % P_;
        int c = (i / P_) % CIN_;
        int b = i / (P_ * CIN_);
        g_xT[(b * P_ + s) * CIN_ + c] = x[i];
    }

    // weight [o][c][k] -> B fragments [kt][jg][ks][lane][uu]
    // uu: 0=Bh reg0, 1=Bh reg1, 2=Bl reg0, 3=Bl reg1 (fp16 hi/lo split)
    for (int i = tid; i < K_ * 8 * 4 * 32 * 4; i += stride) {
        int uu   = i & 3;
        int ln   = (i >> 2) & 31;
        int ks   = (i >> 7) & 3;
        int jg   = (i >> 9) & 7;
        int kt   = i >> 12;
        int reg  = uu & 1;
        int hl   = uu >> 1;
        int n = jg * 8 + (ln >> 2);
        int c = ks * 16 + (ln & 3) * 2 + reg * 8;
        float v0 = w[(n * CIN_ + c) * K_ + kt];
        float v1 = w[(n * CIN_ + c + 1) * K_ + kt];
        __half h0 = __float2half_rn(v0);
        __half h1 = __float2half_rn(v1);
        uint32_t valu;
        if (hl == 0) {
            valu = ((uint32_t)__half_as_ushort(h1) << 16) |
                   (uint32_t)__half_as_ushort(h0);
        } else {
            __half l0 = __float2half_rn(v0 - __half2float(h0));
            __half l1 = __float2half_rn(v1 - __half2float(h1));
            valu = ((uint32_t)__half_as_ushort(l1) << 16) |
                   (uint32_t)__half_as_ushort(l0);
        }
        g_wF[i] = valu;
    }
}

// ---------------- main ----------------
__global__ __launch_bounds__(THREADS, 2)
void deform_hmma_kernel(const float* __restrict__ offset,
                        const float* __restrict__ bias,
                        float* __restrict__ out) {
    extern __shared__ __align__(1024) char smem[];
    const uint32_t sb = smem_u32(smem);

    const int tid  = threadIdx.x;
    const int lane = tid & 31;
    const int warp = tid >> 5;               // 8 warps
    const int blk  = blockIdx.x;
    const int b    = blk >> 7;
    const int p0   = (blk & 127) * MTILE;

    const float* offB = offset + (size_t)b * 3 * K_ * P_;
    const char*  xb   = reinterpret_cast<const char*>(g_xT + (size_t)b * P_ * CIN_);

    // sampling role: 8 points per warp
    const int half = lane >> 4;
    const int c4   = lane & 15;
    const int pl_base = warp * 8;
    const char* base2 = xb + (uint32_t)(c4 << 4);
    uint32_t wAoff[8];
#pragma unroll
    for (int i = 0; i < 8; i++) {
        int pl = pl_base + i;
        wAoff[i] = (uint32_t)(pl * 128 + ((c4 * 8) ^ ((pl & 7) << 4)));
    }

    // mma role: warp (mt, nt) owns D[mt*16..+15][nt*32..+31]
    const int mt = warp >> 1, nt = warp & 1;
    const int rowA = mt * 16 + (lane & 15);
    const uint32_t aBaseOff = (uint32_t)(rowA * 128);
    const uint32_t aXor = (uint32_t)((rowA & 7) << 4);
    const uint32_t aKh  = (uint32_t)((lane >> 4) << 4);

    float acc[4][4];
#pragma unroll
    for (int j = 0; j < 4; j++)
#pragma unroll
        for (int q = 0; q < 4; q++) acc[j][q] = 0.f;

    const uint4* gF = reinterpret_cast<const uint4*>(g_wF);

#pragma unroll 1
    for (int kt = 0; kt < K_; kt++) {
        const int buf = kt & 1;
        char* AP = smem + buf * ABUF;
        const uint32_t AB = sb + buf * ABUF;

        // ---- sampling: 8 points per warp, fp16 single plane ----
        const int kd = kt / 9, kh3 = (kt / 3) % 3, kw3 = kt % 3;
        const float* offk = offB + 3 * kt * P_;

#pragma unroll
        for (int i = 0; i < 8; i++) {
            const int p  = p0 + pl_base + i;
            const int od = p >> 10, oh = (p >> 5) & 31, ow = p & 31;

            float zd = (float)(od - 1 + kd)  + __ldg(offk + p);
            float zh = (float)(oh - 1 + kh3) + __ldg(offk + P_ + p);
            float zw = (float)(ow - 1 + kw3) + __ldg(offk + 2 * P_ + p);

            float fd = floorf(zd); int d0 = (int)fd; float rd = zd - fd;
            float fh = floorf(zh); int h0 = (int)fh; float rh = zh - fh;
            float fw = floorf(zw); int w0 = (int)fw; float rw = zw - fw;

            float wd = half ? (((unsigned)(d0 + 1) < (unsigned)D_) ? rd : 0.f)
                            : (((unsigned)d0 < (unsigned)D_) ? 1.f - rd : 0.f);
            float wh0 = ((unsigned)h0       < (unsigned)H_) ? 1.f - rh : 0.f;
            float wh1 = ((unsigned)(h0 + 1) < (unsigned)H_) ? rh       : 0.f;
            float ww0 = ((unsigned)w0       < (unsigned)W_) ? 1.f - rw : 0.f;
            float ww1 = ((unsigned)(w0 + 1) < (unsigned)W_) ? rw       : 0.f;

            // linear AND-wrap index (wrapped corners carry weight 0)
            const int s0 = (d0 + half) * 1024 + h0 * 32 + w0;
            const uint32_t i0 = ((uint32_t)s0        & 8191u) << 8;
            const uint32_t i1 = ((uint32_t)(s0 + 1)  & 8191u) << 8;
            const uint32_t i2 = ((uint32_t)(s0 + 32) & 8191u) << 8;
            const uint32_t i3 = ((uint32_t)(s0 + 33) & 8191u) << 8;

            const float wdh0 = wd * wh0, wdh1 = wd * wh1;
            const float g0 = wdh0 * ww0, g1 = wdh0 * ww1;
            const float g2 = wdh1 * ww0, g3 = wdh1 * ww1;

            float4 v0 = __ldg(reinterpret_cast<const float4*>(base2 + i0));
            float4 v1 = __ldg(reinterpret_cast<const float4*>(base2 + i1));
            float4 v2 = __ldg(reinterpret_cast<const float4*>(base2 + i2));
            float4 v3 = __ldg(reinterpret_cast<const float4*>(base2 + i3));

            float ax = g0 * v0.x + g1 * v1.x + g2 * v2.x + g3 * v3.x;
            float ay = g0 * v0.y + g1 * v1.y + g2 * v2.y + g3 * v3.y;
            float az = g0 * v0.z + g1 * v1.z + g2 * v2.z + g3 * v3.z;
            float aw = g0 * v0.w + g1 * v1.w + g2 * v2.w + g3 * v3.w;

            ax += __shfl_down_sync(FULL, ax, 16);
            ay += __shfl_down_sync(FULL, ay, 16);
            az += __shfl_down_sync(FULL, az, 16);
            aw += __shfl_down_sync(FULL, aw, 16);

            if (half == 0) {
                uint32_t h01 = f16x2(ay, ax);       // {lo=ch+0, hi=ch+1}
                uint32_t h23 = f16x2(aw, az);
                *reinterpret_cast<uint2*>(AP + wAoff[i]) = make_uint2(h01, h23);
            }
        }

        bar_pair(mt + 1);   // warps {2mt, 2mt+1}: produce rows == consume rows

        // ---- MMA: 4 K-steps, 2 terms (Ah*Bh + Ah*Bl) ----
        const size_t ktBase = (size_t)(kt * 8 + nt * 4) * 128 + lane;
#pragma unroll
        for (int ks = 0; ks < 4; ks++) {
            uint32_t ah[4];
            const uint32_t aoff = aBaseOff + (((uint32_t)(ks * 32) + aKh) ^ aXor);
            ldm_x4(ah, AB + aoff);
#pragma unroll
            for (int j = 0; j < 4; j++) {
                uint4 q = __ldg(gF + ktBase + (size_t)(j * 128 + ks * 32));
                mma_f16(acc[j], ah, q.x, q.y);   // Ah*Bh
                mma_f16(acc[j], ah, q.z, q.w);   // Ah*Bl
            }
        }
        // A buf reuse at kt+2 ordered by bar_pair at kt+1
    }

    // ---- epilogue: D fragment scatter + bias ----
    const int m = lane >> 2;
    const int p = p0 + mt * 16 + m;
#pragma unroll
    for (int j = 0; j < 4; j++) {
        const int n = nt * 32 + j * 8 + 2 * (lane & 3);
        const float bv0 = __ldg(&bias[n]);
        const float bv1 = __ldg(&bias[n + 1]);
        float* o0 = out + ((size_t)(b * COUT_ + n)) * P_ + p;
        o0[0]      = acc[j][0] + bv0;
        o0[P_]     = acc[j][1] + bv1;
        o0[8]      = acc[j][2] + bv0;
        o0[P_ + 8] = acc[j][3] + bv1;
    }
}

extern "C" void kernel_launch(void* const* d_in, const int* in_sizes, int n_in,
                              void* d_out, int out_size) {
    const float* x      = (const float*)d_in[0];
    const float* offset = (const float*)d_in[1];
    const float* weight = (const float*)d_in[2];
    const float* bias   = (const float*)d_in[3];
    float* out = (float*)d_out;

    cudaFuncSetAttribute(deform_hmma_kernel,
                         cudaFuncAttributeMaxDynamicSharedMemorySize, SM_TOTAL);
    prep_kernel<<<256, 256>>>(x, weight);
    deform_hmma_kernel<<<NBLK, THREADS, SM_TOTAL>>>(offset, bias, out);
}

// round 15
// speedup vs baseline: 1.2670x; 1.0971x over previous
#include <cuda_runtime.h>
#include <cuda_fp16.h>
#include <cstdint>

// Deformable Conv3d via portable HMMA — R15: single-term pure fp16 MMA.
//   D = A16 * B16 (both direct fp16 roundings). Measured A-only error was
//   2.06e-4; adding B rounding predicts ~2.9e-4, still 3.4x under 1e-3.
//   Halves MMA count and B-fragment traffic vs R14.
//   MTILE=64 / 256 thr / 256 blocks -> 2 independent blocks per SM;
//   per-warp-pair named barriers only.

namespace {
constexpr int B_ = 2, CIN_ = 64, COUT_ = 64, D_ = 8, H_ = 32, W_ = 32, K_ = 27;
constexpr int P_ = D_ * H_ * W_;              // 8192
constexpr int MTILE = 64;
constexpr int THREADS = 256;
constexpr int NBLK = (B_ * P_) / MTILE;       // 256

constexpr int ABUF = 8192;                    // one A buffer (fp16, 64x128B)
constexpr int SM_TOTAL = 2 * ABUF;            // 16384
constexpr unsigned FULL = 0xffffffffu;
}

__device__ __align__(256) float g_xT[B_ * P_ * CIN_];   // channels-last x
// B fragments, uint4 units: [kt][jg(8)][kp(2)][lane(32)]
//   = {ks_even.reg0, ks_even.reg1, ks_odd.reg0, ks_odd.reg1} (fp16x2 each)
__device__ __align__(256) uint32_t g_wF[K_ * 8 * 2 * 32 * 4];

// ---------------- helpers ----------------
__device__ __forceinline__ uint32_t smem_u32(const void* p) {
    uint32_t a;
    asm("{ .reg .u64 t; cvta.to.shared.u64 t, %1; cvt.u32.u64 %0, t; }"
        : "=r"(a) : "l"(p));
    return a;
}
__device__ __forceinline__ uint32_t f16x2(float hi_elem, float lo_elem) {
    uint32_t r;
    asm("cvt.rn.f16x2.f32 %0, %1, %2;" : "=r"(r) : "f"(hi_elem), "f"(lo_elem));
    return r;
}
__device__ __forceinline__ void ldm_x4(uint32_t* r, uint32_t addr) {
    asm volatile("ldmatrix.sync.aligned.m8n8.x4.shared.b16 {%0,%1,%2,%3}, [%4];"
                 : "=r"(r[0]), "=r"(r[1]), "=r"(r[2]), "=r"(r[3]) : "r"(addr));
}
__device__ __forceinline__ void mma_f16(float* c, const uint32_t* a,
                                        uint32_t b0, uint32_t b1) {
    asm volatile(
        "mma.sync.aligned.m16n8k16.row.col.f32.f16.f16.f32 "
        "{%0,%1,%2,%3}, {%4,%5,%6,%7}, {%8,%9}, {%0,%1,%2,%3};"
        : "+f"(c[0]), "+f"(c[1]), "+f"(c[2]), "+f"(c[3])
        : "r"(a[0]), "r"(a[1]), "r"(a[2]), "r"(a[3]), "r"(b0), "r"(b1));
}
__device__ __forceinline__ void bar_pair(int id) {
    asm volatile("bar.sync %0, 64;" :: "r"(id) : "memory");
}

// ---------------- prep ----------------
__global__ void prep_kernel(const float* __restrict__ x,
                            const float* __restrict__ w) {
    const int stride = gridDim.x * blockDim.x;
    const int tid = blockIdx.x * blockDim.x + threadIdx.x;

    // x [b][c][p] -> xT [b][p][c]
    for (int i = tid; i < B_ * CIN_ * P_; i += stride) {
        int s = i % P_;
        int c = (i / P_) % CIN_;
        int b = i / (P_ * CIN_);
        g_xT[(b * P_ + s) * CIN_ + c] = x[i];
    }

    // weight [o][c][k] -> B fragments [kt][jg][kp][lane][uu]
    // uu: 0 = ks_even reg0, 1 = ks_even reg1, 2 = ks_odd reg0, 3 = ks_odd reg1
    for (int i = tid; i < K_ * 8 * 2 * 32 * 4; i += stride) {
        int uu = i & 3;
        int ln = (i >> 2) & 31;
        int kp = (i >> 7) & 1;
        int jg = (i >> 8) & 7;
        int kt = i >> 11;
        int ks  = kp * 2 + (uu >> 1);
        int reg = uu & 1;
        int n = jg * 8 + (ln >> 2);
        int c = ks * 16 + (ln & 3) * 2 + reg * 8;
        float v0 = w[(n * CIN_ + c) * K_ + kt];
        float v1 = w[(n * CIN_ + c + 1) * K_ + kt];
        __half h0 = __float2half_rn(v0);
        __half h1 = __float2half_rn(v1);
        g_wF[i] = ((uint32_t)__half_as_ushort(h1) << 16) |
                  (uint32_t)__half_as_ushort(h0);
    }
}

// ---------------- main ----------------
__global__ __launch_bounds__(THREADS, 2)
void deform_hmma_kernel(const float* __restrict__ offset,
                        const float* __restrict__ bias,
                        float* __restrict__ out) {
    extern __shared__ __align__(1024) char smem[];
    const uint32_t sb = smem_u32(smem);

    const int tid  = threadIdx.x;
    const int lane = tid & 31;
    const int warp = tid >> 5;               // 8 warps
    const int blk  = blockIdx.x;
    const int b    = blk >> 7;
    const int p0   = (blk & 127) * MTILE;

    const float* offB = offset + (size_t)b * 3 * K_ * P_;
    const char*  xb   = reinterpret_cast<const char*>(g_xT + (size_t)b * P_ * CIN_);

    // sampling role: 8 points per warp
    const int half = lane >> 4;
    const int c4   = lane & 15;
    const int pl_base = warp * 8;
    const char* base2 = xb + (uint32_t)(c4 << 4);
    uint32_t wAoff[8];
#pragma unroll
    for (int i = 0; i < 8; i++) {
        int pl = pl_base + i;
        wAoff[i] = (uint32_t)(pl * 128 + ((c4 * 8) ^ ((pl & 7) << 4)));
    }

    // mma role: warp (mt, nt) owns D[mt*16..+15][nt*32..+31]
    const int mt = warp >> 1, nt = warp & 1;
    const int rowA = mt * 16 + (lane & 15);
    const uint32_t aBaseOff = (uint32_t)(rowA * 128);
    const uint32_t aXor = (uint32_t)((rowA & 7) << 4);
    const uint32_t aKh  = (uint32_t)((lane >> 4) << 4);

    float acc[4][4];
#pragma unroll
    for (int j = 0; j < 4; j++)
#pragma unroll
        for (int q = 0; q < 4; q++) acc[j][q] = 0.f;

    const uint4* gF = reinterpret_cast<const uint4*>(g_wF);

#pragma unroll 1
    for (int kt = 0; kt < K_; kt++) {
        const int buf = kt & 1;
        char* AP = smem + buf * ABUF;
        const uint32_t AB = sb + buf * ABUF;

        // ---- sampling: 8 points per warp, fp16 single plane ----
        const int kd = kt / 9, kh3 = (kt / 3) % 3, kw3 = kt % 3;
        const float* offk = offB + 3 * kt * P_;

#pragma unroll
        for (int i = 0; i < 8; i++) {
            const int p  = p0 + pl_base + i;
            const int od = p >> 10, oh = (p >> 5) & 31, ow = p & 31;

            float zd = (float)(od - 1 + kd)  + __ldg(offk + p);
            float zh = (float)(oh - 1 + kh3) + __ldg(offk + P_ + p);
            float zw = (float)(ow - 1 + kw3) + __ldg(offk + 2 * P_ + p);

            float fd = floorf(zd); int d0 = (int)fd; float rd = zd - fd;
            float fh = floorf(zh); int h0 = (int)fh; float rh = zh - fh;
            float fw = floorf(zw); int w0 = (int)fw; float rw = zw - fw;

            float wd = half ? (((unsigned)(d0 + 1) < (unsigned)D_) ? rd : 0.f)
                            : (((unsigned)d0 < (unsigned)D_) ? 1.f - rd : 0.f);
            float wh0 = ((unsigned)h0       < (unsigned)H_) ? 1.f - rh : 0.f;
            float wh1 = ((unsigned)(h0 + 1) < (unsigned)H_) ? rh       : 0.f;
            float ww0 = ((unsigned)w0       < (unsigned)W_) ? 1.f - rw : 0.f;
            float ww1 = ((unsigned)(w0 + 1) < (unsigned)W_) ? rw       : 0.f;

            // linear AND-wrap index (wrapped corners carry weight 0)
            const int s0 = (d0 + half) * 1024 + h0 * 32 + w0;
            const uint32_t i0 = ((uint32_t)s0        & 8191u) << 8;
            const uint32_t i1 = ((uint32_t)(s0 + 1)  & 8191u) << 8;
            const uint32_t i2 = ((uint32_t)(s0 + 32) & 8191u) << 8;
            const uint32_t i3 = ((uint32_t)(s0 + 33) & 8191u) << 8;

            const float wdh0 = wd * wh0, wdh1 = wd * wh1;
            const float g0 = wdh0 * ww0, g1 = wdh0 * ww1;
            const float g2 = wdh1 * ww0, g3 = wdh1 * ww1;

            float4 v0 = __ldg(reinterpret_cast<const float4*>(base2 + i0));
            float4 v1 = __ldg(reinterpret_cast<const float4*>(base2 + i1));
            float4 v2 = __ldg(reinterpret_cast<const float4*>(base2 + i2));
            float4 v3 = __ldg(reinterpret_cast<const float4*>(base2 + i3));

            float ax = g0 * v0.x + g1 * v1.x + g2 * v2.x + g3 * v3.x;
            float ay = g0 * v0.y + g1 * v1.y + g2 * v2.y + g3 * v3.y;
            float az = g0 * v0.z + g1 * v1.z + g2 * v2.z + g3 * v3.z;
            float aw = g0 * v0.w + g1 * v1.w + g2 * v2.w + g3 * v3.w;

            ax += __shfl_down_sync(FULL, ax, 16);
            ay += __shfl_down_sync(FULL, ay, 16);
            az += __shfl_down_sync(FULL, az, 16);
            aw += __shfl_down_sync(FULL, aw, 16);

            if (half == 0) {
                uint32_t h01 = f16x2(ay, ax);       // {lo=ch+0, hi=ch+1}
                uint32_t h23 = f16x2(aw, az);
                *reinterpret_cast<uint2*>(AP + wAoff[i]) = make_uint2(h01, h23);
            }
        }

        bar_pair(mt + 1);   // warps {2mt, 2mt+1}: produce rows == consume rows

        // ---- MMA: 2 k-step pairs, single term ----
        const size_t ktBase = (size_t)kt * 512 + (size_t)(nt * 4) * 64 + lane;
#pragma unroll
        for (int kp = 0; kp < 2; kp++) {
            uint32_t ah0[4], ah1[4];
            const uint32_t ao0 = aBaseOff + (((uint32_t)(kp * 64) + aKh) ^ aXor);
            const uint32_t ao1 = aBaseOff + (((uint32_t)(kp * 64 + 32) + aKh) ^ aXor);
            ldm_x4(ah0, AB + ao0);
            ldm_x4(ah1, AB + ao1);
#pragma unroll
            for (int j = 0; j < 4; j++) {
                uint4 q = __ldg(gF + ktBase + (size_t)(j * 64 + kp * 32));
                mma_f16(acc[j], ah0, q.x, q.y);   // ks even
                mma_f16(acc[j], ah1, q.z, q.w);   // ks odd
            }
        }
        // A buf reuse at kt+2 ordered by bar_pair at kt+1
    }

    // ---- epilogue: D fragment scatter + bias ----
    const int m = lane >> 2;
    const int p = p0 + mt * 16 + m;
#pragma unroll
    for (int j = 0; j < 4; j++) {
        const int n = nt * 32 + j * 8 + 2 * (lane & 3);
        const float bv0 = __ldg(&bias[n]);
        const float bv1 = __ldg(&bias[n + 1]);
        float* o0 = out + ((size_t)(b * COUT_ + n)) * P_ + p;
        o0[0]      = acc[j][0] + bv0;
        o0[P_]     = acc[j][1] + bv1;
        o0[8]      = acc[j][2] + bv0;
        o0[P_ + 8] = acc[j][3] + bv1;
    }
}

extern "C" void kernel_launch(void* const* d_in, const int* in_sizes, int n_in,
                              void* d_out, int out_size) {
    const float* x      = (const float*)d_in[0];
    const float* offset = (const float*)d_in[1];
    const float* weight = (const float*)d_in[2];
    const float* bias   = (const float*)d_in[3];
    float* out = (float*)d_out;

    cudaFuncSetAttribute(deform_hmma_kernel,
                         cudaFuncAttributeMaxDynamicSharedMemorySize, SM_TOTAL);
    prep_kernel<<<256, 256>>>(x, weight);
    deform_hmma_kernel<<<NBLK, THREADS, SM_TOTAL>>>(offset, bias, out);
}

// round 16
// speedup vs baseline: 1.4250x; 1.1247x over previous
#include <cuda_runtime.h>
#include <cuda_fp16.h>
#include <cstdint>

// Deformable Conv3d via portable HMMA — R16: half-warp-per-point sampling.
//   Lanes 0-15 sample point 2i, lanes 16-31 sample point 2i+1: each lane
//   gathers all 8 trilinear corners of its 16B channel chunk. No shuffles;
//   per-point scalar math executes half as often. fp16 single-term MMA (R15).
//   MTILE=64 / 256 thr / 256 blocks -> 2 independent blocks per SM.

namespace {
constexpr int B_ = 2, CIN_ = 64, COUT_ = 64, D_ = 8, H_ = 32, W_ = 32, K_ = 27;
constexpr int P_ = D_ * H_ * W_;              // 8192
constexpr int MTILE = 64;
constexpr int THREADS = 256;
constexpr int NBLK = (B_ * P_) / MTILE;       // 256

constexpr int ABUF = 8192;                    // one A buffer (fp16, 64x128B)
constexpr int SM_TOTAL = 2 * ABUF;            // 16384
}

__device__ __align__(256) float g_xT[B_ * P_ * CIN_];   // channels-last x
// B fragments, uint4 units: [kt][jg(8)][kp(2)][lane(32)]
//   = {ks_even.reg0, ks_even.reg1, ks_odd.reg0, ks_odd.reg1} (fp16x2 each)
__device__ __align__(256) uint32_t g_wF[K_ * 8 * 2 * 32 * 4];

// ---------------- helpers ----------------
__device__ __forceinline__ uint32_t smem_u32(const void* p) {
    uint32_t a;
    asm("{ .reg .u64 t; cvta.to.shared.u64 t, %1; cvt.u32.u64 %0, t; }"
        : "=r"(a) : "l"(p));
    return a;
}
__device__ __forceinline__ uint32_t f16x2(float hi_elem, float lo_elem) {
    uint32_t r;
    asm("cvt.rn.f16x2.f32 %0, %1, %2;" : "=r"(r) : "f"(hi_elem), "f"(lo_elem));
    return r;
}
__device__ __forceinline__ void ldm_x4(uint32_t* r, uint32_t addr) {
    asm volatile("ldmatrix.sync.aligned.m8n8.x4.shared.b16 {%0,%1,%2,%3}, [%4];"
                 : "=r"(r[0]), "=r"(r[1]), "=r"(r[2]), "=r"(r[3]) : "r"(addr));
}
__device__ __forceinline__ void mma_f16(float* c, const uint32_t* a,
                                        uint32_t b0, uint32_t b1) {
    asm volatile(
        "mma.sync.aligned.m16n8k16.row.col.f32.f16.f16.f32 "
        "{%0,%1,%2,%3}, {%4,%5,%6,%7}, {%8,%9}, {%0,%1,%2,%3};"
        : "+f"(c[0]), "+f"(c[1]), "+f"(c[2]), "+f"(c[3])
        : "r"(a[0]), "r"(a[1]), "r"(a[2]), "r"(a[3]), "r"(b0), "r"(b1));
}
__device__ __forceinline__ void bar_pair(int id) {
    asm volatile("bar.sync %0, 64;" :: "r"(id) : "memory");
}

// ---------------- prep (unchanged from R15) ----------------
__global__ void prep_kernel(const float* __restrict__ x,
                            const float* __restrict__ w) {
    const int stride = gridDim.x * blockDim.x;
    const int tid = blockIdx.x * blockDim.x + threadIdx.x;

    for (int i = tid; i < B_ * CIN_ * P_; i += stride) {
        int s = i % P_;
        int c = (i / P_) % CIN_;
        int b = i / (P_ * CIN_);
        g_xT[(b * P_ + s) * CIN_ + c] = x[i];
    }

    for (int i = tid; i < K_ * 8 * 2 * 32 * 4; i += stride) {
        int uu = i & 3;
        int ln = (i >> 2) & 31;
        int kp = (i >> 7) & 1;
        int jg = (i >> 8) & 7;
        int kt = i >> 11;
        int ks  = kp * 2 + (uu >> 1);
        int reg = uu & 1;
        int n = jg * 8 + (ln >> 2);
        int c = ks * 16 + (ln & 3) * 2 + reg * 8;
        float v0 = w[(n * CIN_ + c) * K_ + kt];
        float v1 = w[(n * CIN_ + c + 1) * K_ + kt];
        __half h0 = __float2half_rn(v0);
        __half h1 = __float2half_rn(v1);
        g_wF[i] = ((uint32_t)__half_as_ushort(h1) << 16) |
                  (uint32_t)__half_as_ushort(h0);
    }
}

// ---------------- main ----------------
__global__ __launch_bounds__(THREADS, 2)
void deform_hmma_kernel(const float* __restrict__ offset,
                        const float* __restrict__ bias,
                        float* __restrict__ out) {
    extern __shared__ __align__(1024) char smem[];
    const uint32_t sb = smem_u32(smem);

    const int tid  = threadIdx.x;
    const int lane = tid & 31;
    const int warp = tid >> 5;               // 8 warps
    const int blk  = blockIdx.x;
    const int b    = blk >> 7;
    const int p0   = (blk & 127) * MTILE;

    const float* offB = offset + (size_t)b * 3 * K_ * P_;
    const char*  xb   = reinterpret_cast<const char*>(g_xT + (size_t)b * P_ * CIN_);

    // sampling role: half-warp = one point; 4 passes x 2 points per tap
    const int hp   = lane >> 4;              // which point of the pair
    const int c4   = lane & 15;              // 16B channel chunk
    const int pl_base = warp * 8;
    const char* base2 = xb + (uint32_t)(c4 << 4);

    // per-pass constants (own point)
    int   pg[4];
    float odf[4], ohf[4], owf[4];
    uint32_t wAoff[4];
#pragma unroll
    for (int i = 0; i < 4; i++) {
        const int pl = pl_base + 2 * i + hp;
        const int p  = p0 + pl;
        pg[i]  = p;
        odf[i] = (float)((p >> 10) - 1);
        ohf[i] = (float)(((p >> 5) & 31) - 1);
        owf[i] = (float)((p & 31) - 1);
        wAoff[i] = (uint32_t)(pl * 128 + ((c4 * 8) ^ ((pl & 7) << 4)));
    }

    // mma role: warp (mt, nt) owns D[mt*16..+15][nt*32..+31]
    const int mt = warp >> 1, nt = warp & 1;
    const int rowA = mt * 16 + (lane & 15);
    const uint32_t aBaseOff = (uint32_t)(rowA * 128);
    const uint32_t aXor = (uint32_t)((rowA & 7) << 4);
    const uint32_t aKh  = (uint32_t)((lane >> 4) << 4);

    float acc[4][4];
#pragma unroll
    for (int j = 0; j < 4; j++)
#pragma unroll
        for (int q = 0; q < 4; q++) acc[j][q] = 0.f;

    const uint4* gF = reinterpret_cast<const uint4*>(g_wF);

#pragma unroll 1
    for (int kt = 0; kt < K_; kt++) {
        const int buf = kt & 1;
        char* AP = smem + buf * ABUF;
        const uint32_t AB = sb + buf * ABUF;

        // ---- sampling: 4 passes, each half-warp samples its own point ----
        const float kdf = (float)(kt / 9);
        const float khf = (float)((kt / 3) % 3);
        const float kwf = (float)(kt % 3);
        const float* offk = offB + 3 * kt * P_;

#pragma unroll
        for (int i = 0; i < 4; i++) {
            const int p = pg[i];

            float zd = odf[i] + kdf + __ldg(offk + p);
            float zh = ohf[i] + khf + __ldg(offk + P_ + p);
            float zw = owf[i] + kwf + __ldg(offk + 2 * P_ + p);

            float fd = floorf(zd); int d0 = (int)fd; float rd = zd - fd;
            float fh = floorf(zh); int h0 = (int)fh; float rh = zh - fh;
            float fw = floorf(zw); int w0 = (int)fw; float rw = zw - fw;

            float wd0 = ((unsigned)d0       < (unsigned)D_) ? 1.f - rd : 0.f;
            float wd1 = ((unsigned)(d0 + 1) < (unsigned)D_) ? rd       : 0.f;
            float wh0 = ((unsigned)h0       < (unsigned)H_) ? 1.f - rh : 0.f;
            float wh1 = ((unsigned)(h0 + 1) < (unsigned)H_) ? rh       : 0.f;
            float ww0 = ((unsigned)w0       < (unsigned)W_) ? 1.f - rw : 0.f;
            float ww1 = ((unsigned)(w0 + 1) < (unsigned)W_) ? rw       : 0.f;

            // linear AND-wrap indices for the 8 corners (wgt 0 if wrapped)
            const int s0 = d0 * 1024 + h0 * 32 + w0;
            uint32_t ix[8];
#pragma unroll
            for (int j = 0; j < 8; j++) {
                const int djj = (j >> 2) * 1024 + (((j >> 1) & 1) * 32) + (j & 1);
                ix[j] = ((uint32_t)(s0 + djj) & 8191u) << 8;
            }

            float4 v[8];
#pragma unroll
            for (int j = 0; j < 8; j++)
                v[j] = __ldg(reinterpret_cast<const float4*>(base2 + ix[j]));

            const float w00 = wd0 * wh0, w01 = wd0 * wh1;
            const float w10 = wd1 * wh0, w11 = wd1 * wh1;
            const float g0 = w00 * ww0, g1 = w00 * ww1;
            const float g2 = w01 * ww0, g3 = w01 * ww1;
            const float g4 = w10 * ww0, g5 = w10 * ww1;
            const float g6 = w11 * ww0, g7 = w11 * ww1;

            float ax = g0 * v[0].x + g1 * v[1].x + g2 * v[2].x + g3 * v[3].x
                     + g4 * v[4].x + g5 * v[5].x + g6 * v[6].x + g7 * v[7].x;
            float ay = g0 * v[0].y + g1 * v[1].y + g2 * v[2].y + g3 * v[3].y
                     + g4 * v[4].y + g5 * v[5].y + g6 * v[6].y + g7 * v[7].y;
            float az = g0 * v[0].z + g1 * v[1].z + g2 * v[2].z + g3 * v[3].z
                     + g4 * v[4].z + g5 * v[5].z + g6 * v[6].z + g7 * v[7].z;
            float aw = g0 * v[0].w + g1 * v[1].w + g2 * v[2].w + g3 * v[3].w
                     + g4 * v[4].w + g5 * v[5].w + g6 * v[6].w + g7 * v[7].w;

            uint32_t h01 = f16x2(ay, ax);       // {lo=ch+0, hi=ch+1}
            uint32_t h23 = f16x2(aw, az);
            *reinterpret_cast<uint2*>(AP + wAoff[i]) = make_uint2(h01, h23);
        }

        bar_pair(mt + 1);   // warps {2mt, 2mt+1}: produce rows == consume rows

        // ---- MMA: 2 k-step pairs, single term (unchanged from R15) ----
        const size_t ktBase = (size_t)kt * 512 + (size_t)(nt * 4) * 64 + lane;
#pragma unroll
        for (int kp = 0; kp < 2; kp++) {
            uint32_t ah0[4], ah1[4];
            const uint32_t ao0 = aBaseOff + (((uint32_t)(kp * 64) + aKh) ^ aXor);
            const uint32_t ao1 = aBaseOff + (((uint32_t)(kp * 64 + 32) + aKh) ^ aXor);
            ldm_x4(ah0, AB + ao0);
            ldm_x4(ah1, AB + ao1);
#pragma unroll
            for (int j = 0; j < 4; j++) {
                uint4 q = __ldg(gF + ktBase + (size_t)(j * 64 + kp * 32));
                mma_f16(acc[j], ah0, q.x, q.y);   // ks even
                mma_f16(acc[j], ah1, q.z, q.w);   // ks odd
            }
        }
        // A buf reuse at kt+2 ordered by bar_pair at kt+1
    }

    // ---- epilogue: D fragment scatter + bias ----
    const int m = lane >> 2;
    const int p = p0 + mt * 16 + m;
#pragma unroll
    for (int j = 0; j < 4; j++) {
        const int n = nt * 32 + j * 8 + 2 * (lane & 3);
        const float bv0 = __ldg(&bias[n]);
        const float bv1 = __ldg(&bias[n + 1]);
        float* o0 = out + ((size_t)(b * COUT_ + n)) * P_ + p;
        o0[0]      = acc[j][0] + bv0;
        o0[P_]     = acc[j][1] + bv1;
        o0[8]      = acc[j][2] + bv0;
        o0[P_ + 8] = acc[j][3] + bv1;
    }
}

extern "C" void kernel_launch(void* const* d_in, const int* in_sizes, int n_in,
                              void* d_out, int out_size) {
    const float* x      = (const float*)d_in[0];
    const float* offset = (const float*)d_in[1];
    const float* weight = (const float*)d_in[2];
    const float* bias   = (const float*)d_in[3];
    float* out = (float*)d_out;

    cudaFuncSetAttribute(deform_hmma_kernel,
                         cudaFuncAttributeMaxDynamicSharedMemorySize, SM_TOTAL);
    prep_kernel<<<256, 256>>>(x, weight);
    deform_hmma_kernel<<<NBLK, THREADS, SM_TOTAL>>>(offset, bias, out);
}